// round 9
// baseline (speedup 1.0000x reference)
#include <cuda_runtime.h>
#include <math.h>
#include <stdint.h>

// ---------------------------------------------------------------------------
// BDH block: B=2, T=2048, D=512, NH=8, N=256, 3 layers.
// tf32 mma.sync m16n8k8, fp32 accumulate.
// cp.async double-buffered tiles; ldmatrix fragment loads; pre-rounded inputs.
// Wide 128x256 block tiles (warp tile 64x64) for the four big GEMMs.
// ---------------------------------------------------------------------------

constexpr int Bb = 2, Tt = 2048, Dd = 512, NHh = 8, Nn = 256;
constexpr int BT = Bb * Tt;        // 4096
constexpr int BH = Bb * NHh;       // 16
constexpr int HN = NHh * Nn;       // 2048
constexpr float LN_EPS = 1e-5f;
constexpr float TWO_PI = 6.283185307179586f;

constexpr int BMT = 128;
constexpr int BKT = 32;
constexpr int A_STAGE = 128 * 36;            // floats per A stage (pad 36)

// smem sizes (bytes) per template instantiation
constexpr int SM_NARROW = 2 * (A_STAGE + 32 * 136) * 4;   // NJ=4, BNK=false: 71680
constexpr int SM_WIDE_KN = 2 * (A_STAGE + 32 * 264) * 4;  // NJ=8, BNK=false: 104448
constexpr int SM_WIDE_NK = 2 * (A_STAGE + 256 * 36) * 4;  // NJ=8, BNK=true : 110592

// Scratch (device globals: no allocation allowed)
__device__ float g_xs   [(size_t)Bb * Tt * Dd];           // full-precision residual stream
__device__ float g_xs_r [(size_t)Bb * Tt * Dd];           // tf32-rounded copy for GEMMs
__device__ float g_tmp  [(size_t)Bb * Tt * Dd];
__device__ float g_xsp  [(size_t)BH * Tt * Nn];           // full precision (gating only)
__device__ float g_qr   [(size_t)BH * Tt * Nn];           // rounded at write
__device__ float g_ykv  [(size_t)BH * Tt * Dd];           // LN writes rounded
__device__ float g_xy   [(size_t)Bb * Tt * NHh * Nn];     // rounded at write
__device__ float g_scores[(size_t)BH * Tt * Tt];          // rounded at write
// Pre-rounded inputs
__device__ float g_x_r  [(size_t)Bb * Tt * Dd];
__device__ float g_win_r[(size_t)Dd * Dd];
__device__ float g_enc_r[(size_t)NHh * Dd * Nn];
__device__ float g_encv_r[(size_t)NHh * Dd * Nn];
__device__ float g_dec_r[(size_t)HN * Dd];
__device__ float g_hw_r [(size_t)Dd * Dd];

__device__ __forceinline__ uint32_t f2tf(float f)
{
    uint32_t u;
    asm("cvt.rna.tf32.f32 %0, %1;" : "=r"(u) : "f"(f));
    return u;
}
__device__ __forceinline__ float rndf(float f) { return __uint_as_float(f2tf(f)); }

__device__ __forceinline__ void cp16(uint32_t saddr, const void* gaddr)
{
    asm volatile("cp.async.cg.shared.global [%0], [%1], 16;" :: "r"(saddr), "l"(gaddr));
}
#define CP_COMMIT() asm volatile("cp.async.commit_group;")
#define CP_WAIT1()  asm volatile("cp.async.wait_group 1;")
#define CP_WAIT0()  asm volatile("cp.async.wait_group 0;")

__device__ __forceinline__ void ldsm_x4(uint32_t* r, uint32_t addr)
{
    asm volatile("ldmatrix.sync.aligned.m8n8.x4.shared.b16 {%0,%1,%2,%3}, [%4];"
                 : "=r"(r[0]), "=r"(r[1]), "=r"(r[2]), "=r"(r[3]) : "r"(addr));
}

// ---------------------------------------------------------------------------
// 128 x (NJ*32) tf32 MMA tile. 256 threads = 8 warps in 2(m) x 4(n);
// warp tile 64 x (NJ*8) = 4 x NJ m16n8k8 frags.  NJ=4 -> BN=128, NJ=8 -> BN=256.
// Inputs MUST already be tf32-rounded fp32 bit patterns.
// acc[mi][nj][e]: e -> {(r,c),(r,c+1),(r+8,c),(r+8,c+1)},
//   r = lane>>2, c = (lane&3)*2 inside fragment (mi*16, nj*8).
// ---------------------------------------------------------------------------
template <int NJ, bool BNK>
__device__ __forceinline__ void mma_tile_t(
    const float* __restrict__ A, int lda,
    const float* __restrict__ Bm, int ldb,
    int kCount, float acc[4][NJ][4])
{
    constexpr int BN = NJ * 32;
    constexpr int B_STRIDE = BNK ? 36 : (BN + 8);
    constexpr int B_STAGE = BNK ? BN * 36 : 32 * (BN + 8);
    constexpr int B_ITERS = BN / 32;          // fill iterations for B
    constexpr int NSEG_SH = (BN == 128) ? 5 : 6;   // log2(BN/4)

    extern __shared__ float sm[];
    float* As = sm;
    float* Bs = sm + 2 * A_STAGE;
    const int tid = threadIdx.x;
    const int lane = tid & 31, warp = tid >> 5;
    const int am = (warp >> 2) * 64, bn = (warp & 3) * (NJ * 8);
    const int ar = lane >> 2, ac = lane & 3;
    const int lrowA = (lane & 7) + 8 * ((lane >> 3) & 1);
    const int lcolA = (lane >> 4) * 4;
    const int lrowB = (lane & 7) + 8 * (lane >> 4);
    const int lcolB = ((lane >> 3) & 1) * 4;

    const uint32_t sA0 = (uint32_t)__cvta_generic_to_shared(As);
    const uint32_t sB0 = (uint32_t)__cvta_generic_to_shared(Bs);

    auto load_stage = [&](int st, int k0) {
        float* Ad = As + st * A_STAGE;
        #pragma unroll
        for (int l = 0; l < 4; l++) {
            int c = tid + l * 256;
            int m = c >> 3, seg = (c & 7) << 2;
            cp16((uint32_t)__cvta_generic_to_shared(Ad + m * 36 + seg),
                 A + (size_t)m * lda + k0 + seg);
        }
        float* Bd = Bs + st * B_STAGE;
        if (BNK) {
            #pragma unroll
            for (int l = 0; l < B_ITERS; l++) {
                int c = tid + l * 256;
                int n = c >> 3, seg = (c & 7) << 2;
                cp16((uint32_t)__cvta_generic_to_shared(Bd + n * 36 + seg),
                     Bm + (size_t)n * ldb + k0 + seg);
            }
        } else {
            #pragma unroll
            for (int l = 0; l < B_ITERS; l++) {
                int c = tid + l * 256;
                int k = c >> NSEG_SH, nseg = (c & ((BN / 4) - 1)) << 2;
                cp16((uint32_t)__cvta_generic_to_shared(Bd + k * B_STRIDE + nseg),
                     Bm + (size_t)(k0 + k) * ldb + nseg);
            }
        }
    };

    const int nT = kCount >> 5;
    load_stage(0, 0);
    CP_COMMIT();

    for (int t = 0; t < nT; t++) {
        const int st = t & 1;
        if (t + 1 < nT) {
            load_stage(st ^ 1, (t + 1) * BKT);
            CP_COMMIT();
            CP_WAIT1();
        } else {
            CP_WAIT0();
        }
        __syncthreads();

        const uint32_t aS = sA0 + st * (A_STAGE * 4);
        const uint32_t bS = sB0 + st * (B_STAGE * 4);
        const float* Bst = Bs + st * B_STAGE;
        #pragma unroll
        for (int kg = 0; kg < 4; kg++) {
            const int kk = kg * 8;
            uint32_t a[4][4], b[NJ][2];
            #pragma unroll
            for (int mi = 0; mi < 4; mi++)
                ldsm_x4(a[mi],
                        aS + (uint32_t)(((am + mi * 16 + lrowA) * 36 + kk + lcolA) * 4));
            if (BNK) {
                #pragma unroll
                for (int g = 0; g < NJ / 2; g++)
                    ldsm_x4(&b[2 * g][0],
                            bS + (uint32_t)(((bn + g * 16 + lrowB) * 36 + kk + lcolB) * 4));
            } else {
                #pragma unroll
                for (int nj = 0; nj < NJ; nj++) {
                    int nb = bn + nj * 8 + ar;
                    b[nj][0] = __float_as_uint(Bst[(size_t)(kk + ac) * B_STRIDE + nb]);
                    b[nj][1] = __float_as_uint(Bst[(size_t)(kk + ac + 4) * B_STRIDE + nb]);
                }
            }
            #pragma unroll
            for (int mi = 0; mi < 4; mi++)
                #pragma unroll
                for (int nj = 0; nj < NJ; nj++)
                    asm volatile(
                        "mma.sync.aligned.m16n8k8.row.col.f32.tf32.tf32.f32 "
                        "{%0,%1,%2,%3}, {%4,%5,%6,%7}, {%8,%9}, {%0,%1,%2,%3};"
                        : "+f"(acc[mi][nj][0]), "+f"(acc[mi][nj][1]),
                          "+f"(acc[mi][nj][2]), "+f"(acc[mi][nj][3])
                        : "r"(a[mi][0]), "r"(a[mi][1]), "r"(a[mi][2]), "r"(a[mi][3]),
                          "r"(b[nj][0]), "r"(b[nj][1]));
        }
        __syncthreads();
    }
}

// Epilogue index helpers (bn computed per-kernel with its NJ)
#define EPI_SETUP(NJv) \
    const int lane = threadIdx.x & 31, warp = threadIdx.x >> 5; \
    const int am = (warp >> 2) * 64, bn = (warp & 3) * ((NJv) * 8); \
    const int er = lane >> 2, ec = (lane & 3) * 2;

// ---------------------------------------------------------------------------
// LN helpers
// ---------------------------------------------------------------------------
__device__ __forceinline__ void block_sum2(float& s, float& q)
{
    __shared__ float shs[8], shq[8];
    __syncthreads();
    #pragma unroll
    for (int o = 16; o > 0; o >>= 1) {
        s += __shfl_xor_sync(0xffffffffu, s, o);
        q += __shfl_xor_sync(0xffffffffu, q, o);
    }
    int w = threadIdx.x >> 5;
    if ((threadIdx.x & 31) == 0) { shs[w] = s; shq[w] = q; }
    __syncthreads();
    s = 0.f; q = 0.f;
    #pragma unroll
    for (int i = 0; i < 8; i++) { s += shs[i]; q += shq[i]; }
}

__device__ __forceinline__ void ln512_pair(float v0, float v1, float& o0, float& o1)
{
    float s = v0 + v1, q = v0 * v0 + v1 * v1;
    block_sum2(s, q);
    float mu  = s * (1.f / 512.f);
    float var = q * (1.f / 512.f) - mu * mu;
    float r   = rsqrtf(var + LN_EPS);
    o0 = (v0 - mu) * r;
    o1 = (v1 - mu) * r;
}

// ---------------------------------------------------------------------------
// Single fused pre-round pass (keeps launch #5 == k_sv for ncu)
// ---------------------------------------------------------------------------
__global__ __launch_bounds__(256) void k_round_all(
    const float* __restrict__ x,   const float* __restrict__ w_in,
    const float* __restrict__ enc, const float* __restrict__ encv,
    const float* __restrict__ dec, const float* __restrict__ hw)
{
    const int stride = gridDim.x * 256;
    int i0 = blockIdx.x * 256 + threadIdx.x;
    for (int i = i0; i < Bb * Tt * Dd; i += stride) g_x_r[i]   = rndf(x[i]);
    for (int i = i0; i < Dd * Dd;      i += stride) g_win_r[i] = rndf(w_in[i]);
    for (int i = i0; i < NHh * Dd * Nn; i += stride) g_enc_r[i]  = rndf(enc[i]);
    for (int i = i0; i < NHh * Dd * Nn; i += stride) g_encv_r[i] = rndf(encv[i]);
    for (int i = i0; i < HN * Dd;      i += stride) g_dec_r[i] = rndf(dec[i]);
    for (int i = i0; i < Dd * Dd;      i += stride) g_hw_r[i]  = rndf(hw[i]);
}

// ---------------------------------------------------------------------------
// Kernels
// ---------------------------------------------------------------------------

__global__ __launch_bounds__(256, 2) void k_inproj(const float* __restrict__ bias)
{
    int n0 = blockIdx.x * 128, m0 = blockIdx.y * BMT;
    float acc[4][4][4] = {};
    mma_tile_t<4, false>(g_x_r + (size_t)m0 * Dd, Dd, g_win_r + n0, Dd, Dd, acc);
    EPI_SETUP(4);
    #pragma unroll
    for (int mi = 0; mi < 4; mi++)
        #pragma unroll
        for (int nj = 0; nj < 4; nj++) {
            int m = m0 + am + mi * 16 + er;
            int n = n0 + bn + nj * 8 + ec;
            g_tmp[(size_t)m * Dd + n]           = acc[mi][nj][0] + bias[n];
            g_tmp[(size_t)m * Dd + n + 1]       = acc[mi][nj][1] + bias[n + 1];
            g_tmp[(size_t)(m + 8) * Dd + n]     = acc[mi][nj][2] + bias[n];
            g_tmp[(size_t)(m + 8) * Dd + n + 1] = acc[mi][nj][3] + bias[n + 1];
        }
}

__global__ __launch_bounds__(256) void k_ln_inproj()
{
    size_t row = blockIdx.x;
    const float* p = g_tmp + row * 512;
    int t = threadIdx.x;
    float o0, o1;
    ln512_pair(p[t], p[t + 256], o0, o1);
    g_xs[row * 512 + t] = o0;
    g_xs[row * 512 + t + 256] = o1;
    g_xs_r[row * 512 + t] = rndf(o0);
    g_xs_r[row * 512 + t + 256] = rndf(o1);
}

// encode + relu + rope (wide: NJ=8, n-tile = 256 = whole N). ec even -> rope pairs.
__global__ __launch_bounds__(256, 1) void k_enc_rope()
{
    int z = blockIdx.z;
    int b = z / NHh, h = z % NHh;
    int m0 = blockIdx.y * BMT;
    const float* A  = g_xs_r + (size_t)b * Tt * Dd + (size_t)m0 * Dd;
    const float* Bm = g_enc_r + (size_t)h * Dd * Nn;
    float acc[4][8][4] = {};
    mma_tile_t<8, false>(A, Dd, Bm, Nn, Dd, acc);
    EPI_SETUP(8);
    #pragma unroll
    for (int mi = 0; mi < 4; mi++)
        #pragma unroll
        for (int nj = 0; nj < 8; nj++) {
            int ne = bn + nj * 8 + ec;
            float freq = exp2f((float)ne * (-1.f / 16.f)) * (1.f / TWO_PI);
            #pragma unroll
            for (int hh = 0; hh < 2; hh++) {
                int t = m0 + am + mi * 16 + er + hh * 8;
                float v0 = fmaxf(acc[mi][nj][hh * 2], 0.f);
                float v1 = fmaxf(acc[mi][nj][hh * 2 + 1], 0.f);
                float ph = (float)t * freq;
                ph = (ph - floorf(ph)) * TWO_PI;
                float sp, cp;
                sincosf(ph, &sp, &cp);
                size_t base = ((size_t)z * Tt + t) * Nn + ne;
                g_xsp[base]     = v0;
                g_xsp[base + 1] = v1;
                g_qr[base]      = rndf(v0 * cp - v1 * sp);
                g_qr[base + 1]  = rndf(v1 * cp + v0 * sp);
            }
        }
}

// scores = QR @ QR^T, strict-lower causal; rounded at write. (wide, BNK)
__global__ __launch_bounds__(256, 1) void k_qk()
{
    int stile = blockIdx.x, ttile = blockIdx.y, z = blockIdx.z;
    if (2 * stile > ttile) return;
    const float* Q  = g_qr + ((size_t)z * Tt + (size_t)ttile * BMT) * Nn;
    const float* Kp = g_qr + ((size_t)z * Tt + (size_t)stile * 256) * Nn;
    float acc[4][8][4] = {};
    mma_tile_t<8, true>(Q, Nn, Kp, Nn, Nn, acc);
    EPI_SETUP(8);
    #pragma unroll
    for (int mi = 0; mi < 4; mi++)
        #pragma unroll
        for (int nj = 0; nj < 8; nj++) {
            int t = ttile * BMT + am + mi * 16 + er;
            int s = stile * 256 + bn + nj * 8 + ec;
            size_t r0 = ((size_t)z * Tt + t) * Tt;
            size_t r1 = ((size_t)z * Tt + t + 8) * Tt;
            g_scores[r0 + s]     = (t > s)     ? rndf(acc[mi][nj][0]) : 0.f;
            g_scores[r0 + s + 1] = (t > s + 1) ? rndf(acc[mi][nj][1]) : 0.f;
            g_scores[r1 + s]     = (t + 8 > s)     ? rndf(acc[mi][nj][2]) : 0.f;
            g_scores[r1 + s + 1] = (t + 8 > s + 1) ? rndf(acc[mi][nj][3]) : 0.f;
        }
}

// yKV = scores @ xs (causal K-extent). (wide, d-tile 256)
__global__ __launch_bounds__(256, 1) void k_sv()
{
    int dtile = blockIdx.x, ttile = blockIdx.y, z = blockIdx.z;
    int b = z / NHh;
    const float* A  = g_scores + ((size_t)z * Tt + (size_t)ttile * BMT) * Tt;
    const float* Bm = g_xs_r + (size_t)b * Tt * Dd + dtile * 256;
    float acc[4][8][4] = {};
    mma_tile_t<8, false>(A, Tt, Bm, Dd, (ttile + 1) * BMT, acc);
    EPI_SETUP(8);
    #pragma unroll
    for (int mi = 0; mi < 4; mi++)
        #pragma unroll
        for (int nj = 0; nj < 8; nj++) {
            int t = ttile * BMT + am + mi * 16 + er;
            int d = dtile * 256 + bn + nj * 8 + ec;
            size_t r0 = ((size_t)z * Tt + t) * Dd;
            size_t r1 = ((size_t)z * Tt + t + 8) * Dd;
            g_ykv[r0 + d]     = acc[mi][nj][0];
            g_ykv[r0 + d + 1] = acc[mi][nj][1];
            g_ykv[r1 + d]     = acc[mi][nj][2];
            g_ykv[r1 + d + 1] = acc[mi][nj][3];
        }
}

// LN of yKV, rounded at write (feeds GEMM A only).
__global__ __launch_bounds__(256) void k_ln_ykv()
{
    size_t row = blockIdx.x;
    float* p = g_ykv + row * 512;
    int t = threadIdx.x;
    float o0, o1;
    ln512_pair(p[t], p[t + 256], o0, o1);
    p[t] = rndf(o0);
    p[t + 256] = rndf(o1);
}

// y_sparse = relu(ln(yKV) @ encv[h]); xy = x_sparse * y_sparse -> [b,t,h,n]. (wide)
__global__ __launch_bounds__(256, 1) void k_venc_mul()
{
    int z = blockIdx.z;
    int b = z / NHh, h = z % NHh;
    int m0 = blockIdx.y * BMT;
    const float* A  = g_ykv + (size_t)z * Tt * Dd + (size_t)m0 * Dd;
    const float* Bm = g_encv_r + (size_t)h * Dd * Nn;
    float acc[4][8][4] = {};
    mma_tile_t<8, false>(A, Dd, Bm, Nn, Dd, acc);
    EPI_SETUP(8);
    #pragma unroll
    for (int mi = 0; mi < 4; mi++)
        #pragma unroll
        for (int nj = 0; nj < 8; nj++) {
            int n = bn + nj * 8 + ec;
            #pragma unroll
            for (int hh = 0; hh < 2; hh++) {
                int t = m0 + am + mi * 16 + er + hh * 8;
                size_t src = ((size_t)z * Tt + t) * Nn + n;
                size_t dst = (((size_t)(b * Tt + t)) * NHh + h) * Nn + n;
                float y0 = fmaxf(acc[mi][nj][hh * 2], 0.f);
                float y1 = fmaxf(acc[mi][nj][hh * 2 + 1], 0.f);
                g_xy[dst]     = rndf(y0 * g_xsp[src]);
                g_xy[dst + 1] = rndf(y1 * g_xsp[src + 1]);
            }
        }
}

// yMLP = xy[4096,2048] @ decoder[2048,512] -> g_tmp (full precision out)
__global__ __launch_bounds__(256, 2) void k_dec()
{
    int n0 = blockIdx.x * 128, m0 = blockIdx.y * BMT;
    float acc[4][4][4] = {};
    mma_tile_t<4, false>(g_xy + (size_t)m0 * HN, HN, g_dec_r + n0, Dd, HN, acc);
    EPI_SETUP(4);
    #pragma unroll
    for (int mi = 0; mi < 4; mi++)
        #pragma unroll
        for (int nj = 0; nj < 4; nj++) {
            int m = m0 + am + mi * 16 + er;
            int n = n0 + bn + nj * 8 + ec;
            g_tmp[(size_t)m * Dd + n]           = acc[mi][nj][0];
            g_tmp[(size_t)m * Dd + n + 1]       = acc[mi][nj][1];
            g_tmp[(size_t)(m + 8) * Dd + n]     = acc[mi][nj][2];
            g_tmp[(size_t)(m + 8) * Dd + n + 1] = acc[mi][nj][3];
        }
}

__global__ __launch_bounds__(256) void k_resid_ln()
{
    size_t row = blockIdx.x;
    const float* a = g_xs + row * 512;
    const float* bp = g_tmp + row * 512;
    int t = threadIdx.x;
    float l0, l1;
    ln512_pair(bp[t], bp[t + 256], l0, l1);
    float t0 = a[t] + l0, t1 = a[t + 256] + l1;
    float o0, o1;
    ln512_pair(t0, t1, o0, o1);
    g_xs[row * 512 + t] = o0;
    g_xs[row * 512 + t + 256] = o1;
    g_xs_r[row * 512 + t] = rndf(o0);
    g_xs_r[row * 512 + t + 256] = rndf(o1);
}

__global__ __launch_bounds__(256, 2) void k_head(
    const float* __restrict__ hb, float* __restrict__ out)
{
    int n0 = blockIdx.x * 128, m0 = blockIdx.y * BMT;
    float acc[4][4][4] = {};
    mma_tile_t<4, false>(g_xs_r + (size_t)m0 * Dd, Dd, g_hw_r + n0, Dd, Dd, acc);
    EPI_SETUP(4);
    #pragma unroll
    for (int mi = 0; mi < 4; mi++)
        #pragma unroll
        for (int nj = 0; nj < 4; nj++) {
            int m = m0 + am + mi * 16 + er;
            int n = n0 + bn + nj * 8 + ec;
            out[(size_t)m * Dd + n]           = acc[mi][nj][0] + hb[n];
            out[(size_t)m * Dd + n + 1]       = acc[mi][nj][1] + hb[n + 1];
            out[(size_t)(m + 8) * Dd + n]     = acc[mi][nj][2] + hb[n];
            out[(size_t)(m + 8) * Dd + n + 1] = acc[mi][nj][3] + hb[n + 1];
        }
}

// ---------------------------------------------------------------------------
extern "C" void kernel_launch(void* const* d_in, const int* in_sizes, int n_in,
                              void* d_out, int out_size)
{
    const float* x    = (const float*)d_in[0];
    const float* w_in = (const float*)d_in[1];
    const float* b_in = (const float*)d_in[2];
    const float* enc  = (const float*)d_in[3];
    const float* encv = (const float*)d_in[4];
    const float* dec  = (const float*)d_in[5];
    const float* hw   = (const float*)d_in[6];
    const float* hb   = (const float*)d_in[7];
    float* out = (float*)d_out;

    static bool attr_done = false;
    if (!attr_done) {
        cudaFuncSetAttribute(k_inproj,   cudaFuncAttributeMaxDynamicSharedMemorySize, SM_NARROW);
        cudaFuncSetAttribute(k_dec,      cudaFuncAttributeMaxDynamicSharedMemorySize, SM_NARROW);
        cudaFuncSetAttribute(k_head,     cudaFuncAttributeMaxDynamicSharedMemorySize, SM_NARROW);
        cudaFuncSetAttribute(k_enc_rope, cudaFuncAttributeMaxDynamicSharedMemorySize, SM_WIDE_KN);
        cudaFuncSetAttribute(k_sv,       cudaFuncAttributeMaxDynamicSharedMemorySize, SM_WIDE_KN);
        cudaFuncSetAttribute(k_venc_mul, cudaFuncAttributeMaxDynamicSharedMemorySize, SM_WIDE_KN);
        cudaFuncSetAttribute(k_qk,       cudaFuncAttributeMaxDynamicSharedMemorySize, SM_WIDE_NK);
        attr_done = true;
    }

    dim3 blk(256);

    k_round_all<<<512, 256>>>(x, w_in, enc, encv, dec, hw);

    k_inproj<<<dim3(Dd / 128, BT / BMT), blk, SM_NARROW>>>(b_in);
    k_ln_inproj<<<BT, 256>>>();

    for (int layer = 0; layer < 3; layer++) {
        k_enc_rope<<<dim3(1, Tt / BMT, BH), blk, SM_WIDE_KN>>>();
        k_qk<<<dim3(Tt / 256, Tt / BMT, BH), blk, SM_WIDE_NK>>>();
        k_sv<<<dim3(Dd / 256, Tt / BMT, BH), blk, SM_WIDE_KN>>>();
        k_ln_ykv<<<BH * Tt, 256>>>();
        k_venc_mul<<<dim3(1, Tt / BMT, BH), blk, SM_WIDE_KN>>>();
        k_dec<<<dim3(Dd / 128, BT / BMT), blk, SM_NARROW>>>();
        k_resid_ln<<<BT, 256>>>();
    }

    k_head<<<dim3(Dd / 128, BT / BMT), blk, SM_NARROW>>>(hb, out);
}

// round 10
// speedup vs baseline: 1.1508x; 1.1508x over previous
#include <cuda_runtime.h>
#include <math.h>
#include <stdint.h>

// ---------------------------------------------------------------------------
// BDH block: B=2, T=2048, D=512, NH=8, N=256, 3 layers.
// tf32 mma.sync m16n8k8, fp32 accumulate. 128x128 block tiles, 2 CTAs/SM.
// 3-stage cp.async circular pipeline, ONE barrier per k-tile, depth-2 prefetch.
// ldmatrix fragment loads; all GEMM inputs pre-rounded to tf32 bits.
// ---------------------------------------------------------------------------

constexpr int Bb = 2, Tt = 2048, Dd = 512, NHh = 8, Nn = 256;
constexpr int BT = Bb * Tt;        // 4096
constexpr int BH = Bb * NHh;       // 16
constexpr int HN = NHh * Nn;       // 2048
constexpr float LN_EPS = 1e-5f;
constexpr float TWO_PI = 6.283185307179586f;

#define BMT 128
#define BNT 128
#define BKT 32

constexpr int A_STRIDE = 36;                 // floats per A row (banks 4r mod 32 distinct)
constexpr int B_STRIDE_KN = 136;             // floats per B[k][n] row
constexpr int STAGE_F = 128 * 36;            // 4608 floats per stage (covers both A and B forms)
constexpr int NSTAGE = 3;
constexpr int SMEM_BYTES = 2 * NSTAGE * STAGE_F * 4;   // 110592 B

// Scratch (device globals: no allocation allowed)
__device__ float g_xs   [(size_t)Bb * Tt * Dd];           // full-precision residual stream
__device__ float g_xs_r [(size_t)Bb * Tt * Dd];           // tf32-rounded copy for GEMMs
__device__ float g_tmp  [(size_t)Bb * Tt * Dd];
__device__ float g_xsp  [(size_t)BH * Tt * Nn];           // full precision (gating only)
__device__ float g_qr   [(size_t)BH * Tt * Nn];           // rounded at write
__device__ float g_ykv  [(size_t)BH * Tt * Dd];           // LN writes rounded
__device__ float g_xy   [(size_t)Bb * Tt * NHh * Nn];     // rounded at write
__device__ float g_scores[(size_t)BH * Tt * Tt];          // rounded at write
// Pre-rounded inputs
__device__ float g_x_r  [(size_t)Bb * Tt * Dd];
__device__ float g_win_r[(size_t)Dd * Dd];
__device__ float g_enc_r[(size_t)NHh * Dd * Nn];
__device__ float g_encv_r[(size_t)NHh * Dd * Nn];
__device__ float g_dec_r[(size_t)HN * Dd];
__device__ float g_hw_r [(size_t)Dd * Dd];

__device__ __forceinline__ uint32_t f2tf(float f)
{
    uint32_t u;
    asm("cvt.rna.tf32.f32 %0, %1;" : "=r"(u) : "f"(f));
    return u;
}
__device__ __forceinline__ float rndf(float f) { return __uint_as_float(f2tf(f)); }

__device__ __forceinline__ void cp16(uint32_t saddr, const void* gaddr)
{
    asm volatile("cp.async.cg.shared.global [%0], [%1], 16;" :: "r"(saddr), "l"(gaddr));
}
#define CP_COMMIT() asm volatile("cp.async.commit_group;")
#define CP_WAIT1()  asm volatile("cp.async.wait_group 1;")

__device__ __forceinline__ void ldsm_x4(uint32_t* r, uint32_t addr)
{
    asm volatile("ldmatrix.sync.aligned.m8n8.x4.shared.b16 {%0,%1,%2,%3}, [%4];"
                 : "=r"(r[0]), "=r"(r[1]), "=r"(r[2]), "=r"(r[3]) : "r"(addr));
}

// ---------------------------------------------------------------------------
// 128x128 tf32 MMA tile. 256 threads = 8 warps in 2(m) x 4(n); warp tile
// 64x32 = 4x4 m16n8k8 frags. Inputs MUST be tf32-rounded fp32 bit patterns.
// Pipeline per k-tile: wait_group 1 -> syncthreads -> fill(t+2) -> commit
//   -> compute(t).  (single barrier; overwrite of stage t%3 by a fast warp
//   happens only after the t+1 barrier, i.e. after all warps computed t.)
// acc[mi][nj][e]: e -> {(r,c),(r,c+1),(r+8,c),(r+8,c+1)},
//   r = lane>>2, c = (lane&3)*2 inside fragment (mi*16, nj*8).
// ---------------------------------------------------------------------------
template <bool BNK>
__device__ __forceinline__ void mma_tile128(
    const float* __restrict__ A, int lda,
    const float* __restrict__ Bm, int ldb,
    int kCount, float acc[4][4][4])
{
    extern __shared__ float sm[];
    float* As = sm;                           // [3][4608]
    float* Bs = sm + NSTAGE * STAGE_F;        // [3][4608]
    const int tid = threadIdx.x;
    const int lane = tid & 31, warp = tid >> 5;
    const int am = (warp >> 2) * 64, bn = (warp & 3) * 32;
    const int ar = lane >> 2, ac = lane & 3;
    const int lrowA = (lane & 7) + 8 * ((lane >> 3) & 1);
    const int lcolA = (lane >> 4) * 4;
    const int lrowB = (lane & 7) + 8 * (lane >> 4);
    const int lcolB = ((lane >> 3) & 1) * 4;

    const uint32_t sA0 = (uint32_t)__cvta_generic_to_shared(As);
    const uint32_t sB0 = (uint32_t)__cvta_generic_to_shared(Bs);

    auto load_stage = [&](int st, int k0) {
        float* Ad = As + st * STAGE_F;
        #pragma unroll
        for (int l = 0; l < 4; l++) {
            int c = tid + l * 256;
            int m = c >> 3, seg = (c & 7) << 2;
            cp16((uint32_t)__cvta_generic_to_shared(Ad + m * A_STRIDE + seg),
                 A + (size_t)m * lda + k0 + seg);
        }
        float* Bd = Bs + st * STAGE_F;
        if (BNK) {
            #pragma unroll
            for (int l = 0; l < 4; l++) {
                int c = tid + l * 256;
                int n = c >> 3, seg = (c & 7) << 2;
                cp16((uint32_t)__cvta_generic_to_shared(Bd + n * A_STRIDE + seg),
                     Bm + (size_t)n * ldb + k0 + seg);
            }
        } else {
            #pragma unroll
            for (int l = 0; l < 4; l++) {
                int c = tid + l * 256;
                int k = c >> 5, nseg = (c & 31) << 2;
                cp16((uint32_t)__cvta_generic_to_shared(Bd + k * B_STRIDE_KN + nseg),
                     Bm + (size_t)(k0 + k) * ldb + nseg);
            }
        }
    };

    const int nT = kCount >> 5;
    load_stage(0, 0);
    CP_COMMIT();
    if (nT > 1) load_stage(1, BKT);
    CP_COMMIT();

    int st = 0;
    for (int t = 0; t < nT; t++) {
        CP_WAIT1();
        __syncthreads();
        if (t + 2 < nT) {
            int st2 = st + 2 - ((st + 2 >= NSTAGE) ? NSTAGE : 0);
            load_stage(st2, (t + 2) * BKT);
        }
        CP_COMMIT();

        const uint32_t aS = sA0 + st * (STAGE_F * 4);
        const uint32_t bS = sB0 + st * (STAGE_F * 4);
        const float* Bst = Bs + st * STAGE_F;
        #pragma unroll
        for (int kg = 0; kg < 4; kg++) {
            const int kk = kg * 8;
            uint32_t a[4][4], b[4][2];
            #pragma unroll
            for (int mi = 0; mi < 4; mi++)
                ldsm_x4(a[mi],
                        aS + (uint32_t)(((am + mi * 16 + lrowA) * A_STRIDE + kk + lcolA) * 4));
            if (BNK) {
                ldsm_x4(&b[0][0],
                        bS + (uint32_t)(((bn + lrowB) * A_STRIDE + kk + lcolB) * 4));
                ldsm_x4(&b[2][0],
                        bS + (uint32_t)(((bn + 16 + lrowB) * A_STRIDE + kk + lcolB) * 4));
            } else {
                #pragma unroll
                for (int nj = 0; nj < 4; nj++) {
                    int nb = bn + nj * 8 + ar;
                    b[nj][0] = __float_as_uint(Bst[(size_t)(kk + ac) * B_STRIDE_KN + nb]);
                    b[nj][1] = __float_as_uint(Bst[(size_t)(kk + ac + 4) * B_STRIDE_KN + nb]);
                }
            }
            #pragma unroll
            for (int mi = 0; mi < 4; mi++)
                #pragma unroll
                for (int nj = 0; nj < 4; nj++)
                    asm volatile(
                        "mma.sync.aligned.m16n8k8.row.col.f32.tf32.tf32.f32 "
                        "{%0,%1,%2,%3}, {%4,%5,%6,%7}, {%8,%9}, {%0,%1,%2,%3};"
                        : "+f"(acc[mi][nj][0]), "+f"(acc[mi][nj][1]),
                          "+f"(acc[mi][nj][2]), "+f"(acc[mi][nj][3])
                        : "r"(a[mi][0]), "r"(a[mi][1]), "r"(a[mi][2]), "r"(a[mi][3]),
                          "r"(b[nj][0]), "r"(b[nj][1]));
        }
        st = (st + 1 == NSTAGE) ? 0 : st + 1;
    }
}

// Epilogue index helpers
#define EPI_SETUP \
    const int lane = threadIdx.x & 31, warp = threadIdx.x >> 5; \
    const int am = (warp >> 2) * 64, bn = (warp & 3) * 32; \
    const int er = lane >> 2, ec = (lane & 3) * 2;

// ---------------------------------------------------------------------------
// LN helpers
// ---------------------------------------------------------------------------
__device__ __forceinline__ void block_sum2(float& s, float& q)
{
    __shared__ float shs[8], shq[8];
    __syncthreads();
    #pragma unroll
    for (int o = 16; o > 0; o >>= 1) {
        s += __shfl_xor_sync(0xffffffffu, s, o);
        q += __shfl_xor_sync(0xffffffffu, q, o);
    }
    int w = threadIdx.x >> 5;
    if ((threadIdx.x & 31) == 0) { shs[w] = s; shq[w] = q; }
    __syncthreads();
    s = 0.f; q = 0.f;
    #pragma unroll
    for (int i = 0; i < 8; i++) { s += shs[i]; q += shq[i]; }
}

__device__ __forceinline__ void ln512_pair(float v0, float v1, float& o0, float& o1)
{
    float s = v0 + v1, q = v0 * v0 + v1 * v1;
    block_sum2(s, q);
    float mu  = s * (1.f / 512.f);
    float var = q * (1.f / 512.f) - mu * mu;
    float r   = rsqrtf(var + LN_EPS);
    o0 = (v0 - mu) * r;
    o1 = (v1 - mu) * r;
}

// ---------------------------------------------------------------------------
// Single fused pre-round pass
// ---------------------------------------------------------------------------
__global__ __launch_bounds__(256) void k_round_all(
    const float* __restrict__ x,   const float* __restrict__ w_in,
    const float* __restrict__ enc, const float* __restrict__ encv,
    const float* __restrict__ dec, const float* __restrict__ hw)
{
    const int stride = gridDim.x * 256;
    int i0 = blockIdx.x * 256 + threadIdx.x;
    for (int i = i0; i < Bb * Tt * Dd; i += stride) g_x_r[i]   = rndf(x[i]);
    for (int i = i0; i < Dd * Dd;      i += stride) g_win_r[i] = rndf(w_in[i]);
    for (int i = i0; i < NHh * Dd * Nn; i += stride) g_enc_r[i]  = rndf(enc[i]);
    for (int i = i0; i < NHh * Dd * Nn; i += stride) g_encv_r[i] = rndf(encv[i]);
    for (int i = i0; i < HN * Dd;      i += stride) g_dec_r[i] = rndf(dec[i]);
    for (int i = i0; i < Dd * Dd;      i += stride) g_hw_r[i]  = rndf(hw[i]);
}

// ---------------------------------------------------------------------------
// Kernels
// ---------------------------------------------------------------------------

__global__ __launch_bounds__(256, 2) void k_inproj(const float* __restrict__ bias)
{
    int n0 = blockIdx.x * BNT, m0 = blockIdx.y * BMT;
    float acc[4][4][4] = {};
    mma_tile128<false>(g_x_r + (size_t)m0 * Dd, Dd, g_win_r + n0, Dd, Dd, acc);
    EPI_SETUP;
    #pragma unroll
    for (int mi = 0; mi < 4; mi++)
        #pragma unroll
        for (int nj = 0; nj < 4; nj++) {
            int m = m0 + am + mi * 16 + er;
            int n = n0 + bn + nj * 8 + ec;
            g_tmp[(size_t)m * Dd + n]           = acc[mi][nj][0] + bias[n];
            g_tmp[(size_t)m * Dd + n + 1]       = acc[mi][nj][1] + bias[n + 1];
            g_tmp[(size_t)(m + 8) * Dd + n]     = acc[mi][nj][2] + bias[n];
            g_tmp[(size_t)(m + 8) * Dd + n + 1] = acc[mi][nj][3] + bias[n + 1];
        }
}

__global__ __launch_bounds__(256) void k_ln_inproj()
{
    size_t row = blockIdx.x;
    const float* p = g_tmp + row * 512;
    int t = threadIdx.x;
    float o0, o1;
    ln512_pair(p[t], p[t + 256], o0, o1);
    g_xs[row * 512 + t] = o0;
    g_xs[row * 512 + t + 256] = o1;
    g_xs_r[row * 512 + t] = rndf(o0);
    g_xs_r[row * 512 + t + 256] = rndf(o1);
}

// encode + relu + rope. ec even -> rope pairs.
__global__ __launch_bounds__(256, 2) void k_enc_rope()
{
    int z = blockIdx.z;
    int b = z / NHh, h = z % NHh;
    int n0 = blockIdx.x * BNT, m0 = blockIdx.y * BMT;
    const float* A  = g_xs_r + (size_t)b * Tt * Dd + (size_t)m0 * Dd;
    const float* Bm = g_enc_r + (size_t)h * Dd * Nn + n0;
    float acc[4][4][4] = {};
    mma_tile128<false>(A, Dd, Bm, Nn, Dd, acc);
    EPI_SETUP;
    #pragma unroll
    for (int mi = 0; mi < 4; mi++)
        #pragma unroll
        for (int nj = 0; nj < 4; nj++) {
            int ne = n0 + bn + nj * 8 + ec;
            float freq = exp2f((float)ne * (-1.f / 16.f)) * (1.f / TWO_PI);
            #pragma unroll
            for (int hh = 0; hh < 2; hh++) {
                int t = m0 + am + mi * 16 + er + hh * 8;
                float v0 = fmaxf(acc[mi][nj][hh * 2], 0.f);
                float v1 = fmaxf(acc[mi][nj][hh * 2 + 1], 0.f);
                float ph = (float)t * freq;
                ph = (ph - floorf(ph)) * TWO_PI;
                float sp, cp;
                sincosf(ph, &sp, &cp);
                size_t base = ((size_t)z * Tt + t) * Nn + ne;
                g_xsp[base]     = v0;
                g_xsp[base + 1] = v1;
                g_qr[base]      = rndf(v0 * cp - v1 * sp);
                g_qr[base + 1]  = rndf(v1 * cp + v0 * sp);
            }
        }
}

// scores = QR @ QR^T, strict-lower causal; rounded at write.
__global__ __launch_bounds__(256, 2) void k_qk()
{
    int stile = blockIdx.x, ttile = blockIdx.y, z = blockIdx.z;
    if (stile > ttile) return;
    const float* Q  = g_qr + ((size_t)z * Tt + (size_t)ttile * BMT) * Nn;
    const float* Kp = g_qr + ((size_t)z * Tt + (size_t)stile * BNT) * Nn;
    float acc[4][4][4] = {};
    mma_tile128<true>(Q, Nn, Kp, Nn, Nn, acc);
    EPI_SETUP;
    #pragma unroll
    for (int mi = 0; mi < 4; mi++)
        #pragma unroll
        for (int nj = 0; nj < 4; nj++) {
            int t = ttile * BMT + am + mi * 16 + er;
            int s = stile * BNT + bn + nj * 8 + ec;
            size_t r0 = ((size_t)z * Tt + t) * Tt;
            size_t r1 = ((size_t)z * Tt + t + 8) * Tt;
            g_scores[r0 + s]     = (t > s)     ? rndf(acc[mi][nj][0]) : 0.f;
            g_scores[r0 + s + 1] = (t > s + 1) ? rndf(acc[mi][nj][1]) : 0.f;
            g_scores[r1 + s]     = (t + 8 > s)     ? rndf(acc[mi][nj][2]) : 0.f;
            g_scores[r1 + s + 1] = (t + 8 > s + 1) ? rndf(acc[mi][nj][3]) : 0.f;
        }
}

// yKV = scores @ xs (causal K-extent)
__global__ __launch_bounds__(256, 2) void k_sv()
{
    int dtile = blockIdx.x, ttile = blockIdx.y, z = blockIdx.z;
    int b = z / NHh;
    const float* A  = g_scores + ((size_t)z * Tt + (size_t)ttile * BMT) * Tt;
    const float* Bm = g_xs_r + (size_t)b * Tt * Dd + dtile * BNT;
    float acc[4][4][4] = {};
    mma_tile128<false>(A, Tt, Bm, Dd, (ttile + 1) * BMT, acc);
    EPI_SETUP;
    #pragma unroll
    for (int mi = 0; mi < 4; mi++)
        #pragma unroll
        for (int nj = 0; nj < 4; nj++) {
            int t = ttile * BMT + am + mi * 16 + er;
            int d = dtile * BNT + bn + nj * 8 + ec;
            size_t r0 = ((size_t)z * Tt + t) * Dd;
            size_t r1 = ((size_t)z * Tt + t + 8) * Dd;
            g_ykv[r0 + d]     = acc[mi][nj][0];
            g_ykv[r0 + d + 1] = acc[mi][nj][1];
            g_ykv[r1 + d]     = acc[mi][nj][2];
            g_ykv[r1 + d + 1] = acc[mi][nj][3];
        }
}

// LN of yKV, rounded at write (feeds GEMM A only).
__global__ __launch_bounds__(256) void k_ln_ykv()
{
    size_t row = blockIdx.x;
    float* p = g_ykv + row * 512;
    int t = threadIdx.x;
    float o0, o1;
    ln512_pair(p[t], p[t + 256], o0, o1);
    p[t] = rndf(o0);
    p[t + 256] = rndf(o1);
}

// y_sparse = relu(ln(yKV) @ encv[h]); xy = x_sparse * y_sparse -> [b,t,h,n], rounded.
__global__ __launch_bounds__(256, 2) void k_venc_mul()
{
    int z = blockIdx.z;
    int b = z / NHh, h = z % NHh;
    int n0 = blockIdx.x * BNT, m0 = blockIdx.y * BMT;
    const float* A  = g_ykv + (size_t)z * Tt * Dd + (size_t)m0 * Dd;
    const float* Bm = g_encv_r + (size_t)h * Dd * Nn + n0;
    float acc[4][4][4] = {};
    mma_tile128<false>(A, Dd, Bm, Nn, Dd, acc);
    EPI_SETUP;
    #pragma unroll
    for (int mi = 0; mi < 4; mi++)
        #pragma unroll
        for (int nj = 0; nj < 4; nj++) {
            int n = n0 + bn + nj * 8 + ec;
            #pragma unroll
            for (int hh = 0; hh < 2; hh++) {
                int t = m0 + am + mi * 16 + er + hh * 8;
                size_t src = ((size_t)z * Tt + t) * Nn + n;
                size_t dst = (((size_t)(b * Tt + t)) * NHh + h) * Nn + n;
                float y0 = fmaxf(acc[mi][nj][hh * 2], 0.f);
                float y1 = fmaxf(acc[mi][nj][hh * 2 + 1], 0.f);
                g_xy[dst]     = rndf(y0 * g_xsp[src]);
                g_xy[dst + 1] = rndf(y1 * g_xsp[src + 1]);
            }
        }
}

// yMLP = xy[4096,2048] @ decoder[2048,512] -> g_tmp (full precision out)
__global__ __launch_bounds__(256, 2) void k_dec()
{
    int n0 = blockIdx.x * BNT, m0 = blockIdx.y * BMT;
    float acc[4][4][4] = {};
    mma_tile128<false>(g_xy + (size_t)m0 * HN, HN, g_dec_r + n0, Dd, HN, acc);
    EPI_SETUP;
    #pragma unroll
    for (int mi = 0; mi < 4; mi++)
        #pragma unroll
        for (int nj = 0; nj < 4; nj++) {
            int m = m0 + am + mi * 16 + er;
            int n = n0 + bn + nj * 8 + ec;
            g_tmp[(size_t)m * Dd + n]           = acc[mi][nj][0];
            g_tmp[(size_t)m * Dd + n + 1]       = acc[mi][nj][1];
            g_tmp[(size_t)(m + 8) * Dd + n]     = acc[mi][nj][2];
            g_tmp[(size_t)(m + 8) * Dd + n + 1] = acc[mi][nj][3];
        }
}

__global__ __launch_bounds__(256) void k_resid_ln()
{
    size_t row = blockIdx.x;
    const float* a = g_xs + row * 512;
    const float* bp = g_tmp + row * 512;
    int t = threadIdx.x;
    float l0, l1;
    ln512_pair(bp[t], bp[t + 256], l0, l1);
    float t0 = a[t] + l0, t1 = a[t + 256] + l1;
    float o0, o1;
    ln512_pair(t0, t1, o0, o1);
    g_xs[row * 512 + t] = o0;
    g_xs[row * 512 + t + 256] = o1;
    g_xs_r[row * 512 + t] = rndf(o0);
    g_xs_r[row * 512 + t + 256] = rndf(o1);
}

__global__ __launch_bounds__(256, 2) void k_head(
    const float* __restrict__ hb, float* __restrict__ out)
{
    int n0 = blockIdx.x * BNT, m0 = blockIdx.y * BMT;
    float acc[4][4][4] = {};
    mma_tile128<false>(g_xs_r + (size_t)m0 * Dd, Dd, g_hw_r + n0, Dd, Dd, acc);
    EPI_SETUP;
    #pragma unroll
    for (int mi = 0; mi < 4; mi++)
        #pragma unroll
        for (int nj = 0; nj < 4; nj++) {
            int m = m0 + am + mi * 16 + er;
            int n = n0 + bn + nj * 8 + ec;
            out[(size_t)m * Dd + n]           = acc[mi][nj][0] + hb[n];
            out[(size_t)m * Dd + n + 1]       = acc[mi][nj][1] + hb[n + 1];
            out[(size_t)(m + 8) * Dd + n]     = acc[mi][nj][2] + hb[n];
            out[(size_t)(m + 8) * Dd + n + 1] = acc[mi][nj][3] + hb[n + 1];
        }
}

// ---------------------------------------------------------------------------
extern "C" void kernel_launch(void* const* d_in, const int* in_sizes, int n_in,
                              void* d_out, int out_size)
{
    const float* x    = (const float*)d_in[0];
    const float* w_in = (const float*)d_in[1];
    const float* b_in = (const float*)d_in[2];
    const float* enc  = (const float*)d_in[3];
    const float* encv = (const float*)d_in[4];
    const float* dec  = (const float*)d_in[5];
    const float* hw   = (const float*)d_in[6];
    const float* hb   = (const float*)d_in[7];
    float* out = (float*)d_out;

    static bool attr_done = false;
    if (!attr_done) {
        cudaFuncSetAttribute(k_inproj,   cudaFuncAttributeMaxDynamicSharedMemorySize, SMEM_BYTES);
        cudaFuncSetAttribute(k_enc_rope, cudaFuncAttributeMaxDynamicSharedMemorySize, SMEM_BYTES);
        cudaFuncSetAttribute(k_qk,       cudaFuncAttributeMaxDynamicSharedMemorySize, SMEM_BYTES);
        cudaFuncSetAttribute(k_sv,       cudaFuncAttributeMaxDynamicSharedMemorySize, SMEM_BYTES);
        cudaFuncSetAttribute(k_venc_mul, cudaFuncAttributeMaxDynamicSharedMemorySize, SMEM_BYTES);
        cudaFuncSetAttribute(k_dec,      cudaFuncAttributeMaxDynamicSharedMemorySize, SMEM_BYTES);
        cudaFuncSetAttribute(k_head,     cudaFuncAttributeMaxDynamicSharedMemorySize, SMEM_BYTES);
        attr_done = true;
    }

    dim3 blk(256);

    k_round_all<<<512, 256>>>(x, w_in, enc, encv, dec, hw);

    k_inproj<<<dim3(Dd / BNT, BT / BMT), blk, SMEM_BYTES>>>(b_in);
    k_ln_inproj<<<BT, 256>>>();

    for (int layer = 0; layer < 3; layer++) {
        k_enc_rope<<<dim3(Nn / BNT, Tt / BMT, BH), blk, SMEM_BYTES>>>();
        k_qk<<<dim3(Tt / BNT, Tt / BMT, BH), blk, SMEM_BYTES>>>();
        k_sv<<<dim3(Dd / BNT, Tt / BMT, BH), blk, SMEM_BYTES>>>();
        k_ln_ykv<<<BH * Tt, 256>>>();
        k_venc_mul<<<dim3(Nn / BNT, Tt / BMT, BH), blk, SMEM_BYTES>>>();
        k_dec<<<dim3(Dd / BNT, BT / BMT), blk, SMEM_BYTES>>>();
        k_resid_ln<<<BT, 256>>>();
    }

    k_head<<<dim3(Dd / BNT, BT / BMT), blk, SMEM_BYTES>>>(hb, out);
}